// round 1
// baseline (speedup 1.0000x reference)
#include <cuda_runtime.h>
#include <cuda_bf16.h>
#include <cstdint>
#include <math.h>

// ---------------------------------------------------------------------------
// Problem constants
// ---------------------------------------------------------------------------
#define NNODES 8192
#define FDIM   16
#define HDIM   64
#define GSEG   256
#define LNEPS  1e-3f

// GEMM tiling
#define BM 128
#define BK 32
#define KSPLIT 4096          // split-K = 2
#define LDA 36               // smem row pitch (floats) for A tiles
#define LDB 36               // smem row pitch (floats) for B tiles
#define NIT (KSPLIT / BK)    // 128 k-iterations per CTA

// ---------------------------------------------------------------------------
// Device scratch (no allocations allowed)
// ---------------------------------------------------------------------------
__device__ float dY0T[HDIM * NNODES];      // (X@W0)^T, tf32-rounded
__device__ float dZP[2 * NNODES * HDIM];   // split-K partials of A@Y
__device__ float dH0[NNODES * HDIM];       // layer-0 hidden
__device__ float dY1T[HDIM * NNODES];      // (h0@W1)^T, tf32-rounded
__device__ float dG[GSEG * HDIM];          // attention-pool accumulator
__device__ float dZmax[GSEG];
__device__ float dZsum[GSEG];
__device__ float dZnum[GSEG * 3];

// ---------------------------------------------------------------------------
// Small PTX helpers
// ---------------------------------------------------------------------------
__device__ __forceinline__ uint32_t f2tf(float x) {
    uint32_t r;
    asm("cvt.rna.tf32.f32 %0, %1;" : "=r"(r) : "f"(x));
    return r;
}

__device__ __forceinline__ void ldsm4(uint32_t &r0, uint32_t &r1, uint32_t &r2,
                                      uint32_t &r3, uint32_t addr) {
    asm volatile("ldmatrix.sync.aligned.m8n8.x4.shared.b16 {%0,%1,%2,%3}, [%4];"
                 : "=r"(r0), "=r"(r1), "=r"(r2), "=r"(r3) : "r"(addr));
}

__device__ __forceinline__ void mma_tf32(float c[4], const uint32_t a[4],
                                         const uint32_t b[2]) {
    asm volatile(
        "mma.sync.aligned.m16n8k8.row.col.f32.tf32.tf32.f32 "
        "{%0,%1,%2,%3}, {%4,%5,%6,%7}, {%8,%9}, {%0,%1,%2,%3};"
        : "+f"(c[0]), "+f"(c[1]), "+f"(c[2]), "+f"(c[3])
        : "r"(a[0]), "r"(a[1]), "r"(a[2]), "r"(a[3]), "r"(b[0]), "r"(b[1]));
}

// ---------------------------------------------------------------------------
// init: zero accumulators
// ---------------------------------------------------------------------------
__global__ void init_kernel() {
    int i = blockIdx.x * 256 + threadIdx.x;
    if (i < GSEG * HDIM) dG[i] = 0.f;
    if (i < GSEG) { dZmax[i] = 0.f; dZsum[i] = 0.f; }
    if (i < GSEG * 3) dZnum[i] = 0.f;
}

// ---------------------------------------------------------------------------
// segment max of z = log1p(relu(X[:,0]))  (z >= 0, so int-compare atomicMax ok)
// ---------------------------------------------------------------------------
__global__ void zmax_kernel(const float *__restrict__ X, const int *__restrict__ I) {
    int i = blockIdx.x * 256 + threadIdx.x;
    if (i >= NNODES) return;
    float z = log1pf(fmaxf(X[i * FDIM], 0.f));
    atomicMax((int *)&dZmax[I[i]], __float_as_int(z));
}

// zexp sums + xyz-weighted sums
__global__ void zexp_kernel(const float *__restrict__ X, const int *__restrict__ I) {
    int i = blockIdx.x * 256 + threadIdx.x;
    if (i >= NNODES) return;
    float z = log1pf(fmaxf(X[i * FDIM], 0.f));
    int g = I[i];
    float w = expf(z - dZmax[g]);
    atomicAdd(&dZsum[g], w);
    atomicAdd(&dZnum[g * 3 + 0], w * X[i * FDIM + 13]);
    atomicAdd(&dZnum[g * 3 + 1], w * X[i * FDIM + 14]);
    atomicAdd(&dZnum[g * 3 + 2], w * X[i * FDIM + 15]);
}

// ---------------------------------------------------------------------------
// Y0T[n][i] = round_tf32( sum_f X[i][f] * W0[f][n] )
// block (32,8): 8 rows per block; lane covers n and n+32
// ---------------------------------------------------------------------------
__global__ void y0t_kernel(const float *__restrict__ X, const float *__restrict__ W0) {
    __shared__ float W0s[FDIM][HDIM];
    int lane = threadIdx.x, ty = threadIdx.y;
    int tid = ty * 32 + lane;
#pragma unroll
    for (int j = 0; j < 4; j++) {
        int idx = tid + 256 * j;  // 1024 = 16*64
        W0s[idx >> 6][idx & 63] = W0[idx];
    }
    __syncthreads();
    int row = blockIdx.x * 8 + ty;
    float a0 = 0.f, a1 = 0.f;
#pragma unroll
    for (int f = 0; f < FDIM; f++) {
        float xf = X[row * FDIM + f];
        a0 += xf * W0s[f][lane];
        a1 += xf * W0s[f][lane + 32];
    }
    dY0T[(size_t)lane * NNODES + row] = __uint_as_float(f2tf(a0));
    dY0T[(size_t)(lane + 32) * NNODES + row] = __uint_as_float(f2tf(a1));
}

// ---------------------------------------------------------------------------
// tf32 tensor-core GEMM: C_partial[s] = A[:, s*4096:(s+1)*4096] @ BT^T
//   A  : [8192, 8192] row-major f32 (rounded to tf32-RN in staging)
//   BT : [64, 8192]  row-major, already tf32-rounded
//   C  : dZP, blockIdx.y selects partial buffer
// ---------------------------------------------------------------------------
__global__ void __launch_bounds__(256)
gemm_tf32(const float *__restrict__ A, const float *__restrict__ BT,
          float *__restrict__ C) {
    extern __shared__ float smem[];
    float *As = smem;                 // [2][BM][LDA]
    float *Bs = smem + 2 * BM * LDA;  // [2][64][LDB]

    const int tid = threadIdx.x;
    const int lane = tid & 31, wid = tid >> 5;
    const int wm = wid & 3, wn = wid >> 2;  // 4 m-warps x 2 n-warps
    const int m0 = blockIdx.x * BM;
    const int kbeg = blockIdx.y * KSPLIT;

    float4 areg[4];
    float4 breg[2];
    float c[2][4][4] = {};

    // ldmatrix lane-derived offsets
    const int arow = wm * 32 + (lane & 7) + ((lane >> 3) & 1) * 8;
    const int acoff = ((lane >> 4) & 1) * 4;
    const int brow = wn * 32 + (lane & 7) + ((lane >> 4) & 1) * 8;
    const int bcoff = ((lane >> 3) & 1) * 4;

#define GEMM_LDG(KB)                                                          \
    do {                                                                      \
        _Pragma("unroll") for (int j = 0; j < 4; j++) {                       \
            int idx = tid + 256 * j;                                          \
            int r = idx >> 3, c4 = idx & 7;                                   \
            areg[j] = *(const float4 *)(A + (size_t)(m0 + r) * NNODES + (KB) + c4 * 4); \
        }                                                                     \
        _Pragma("unroll") for (int j = 0; j < 2; j++) {                       \
            int idx = tid + 256 * j;                                          \
            int n = idx >> 3, c4 = idx & 7;                                   \
            breg[j] = *(const float4 *)(BT + (size_t)n * NNODES + (KB) + c4 * 4); \
        }                                                                     \
    } while (0)

#define GEMM_STS(BUF)                                                         \
    do {                                                                      \
        float *ab = As + (BUF) * BM * LDA;                                    \
        _Pragma("unroll") for (int j = 0; j < 4; j++) {                       \
            int idx = tid + 256 * j;                                          \
            int r = idx >> 3, c4 = idx & 7;                                   \
            uint4 u;                                                          \
            u.x = f2tf(areg[j].x); u.y = f2tf(areg[j].y);                     \
            u.z = f2tf(areg[j].z); u.w = f2tf(areg[j].w);                     \
            *(uint4 *)(ab + r * LDA + c4 * 4) = u;                            \
        }                                                                     \
        float *bb = Bs + (BUF) * 64 * LDB;                                    \
        _Pragma("unroll") for (int j = 0; j < 2; j++) {                       \
            int idx = tid + 256 * j;                                          \
            int n = idx >> 3, c4 = idx & 7;                                   \
            *(float4 *)(bb + n * LDB + c4 * 4) = breg[j];                     \
        }                                                                     \
    } while (0)

#define GEMM_COMPUTE(BUF)                                                     \
    do {                                                                      \
        uint32_t abase = (uint32_t)__cvta_generic_to_shared(As + (BUF) * BM * LDA); \
        uint32_t bbase = (uint32_t)__cvta_generic_to_shared(Bs + (BUF) * 64 * LDB); \
        _Pragma("unroll") for (int ks = 0; ks < 4; ks++) {                    \
            int k0 = ks * 8;                                                  \
            uint32_t a[2][4], b[4][2];                                        \
            _Pragma("unroll") for (int mi = 0; mi < 2; mi++) {                \
                uint32_t addr = abase + ((arow + mi * 16) * LDA + k0 + acoff) * 4; \
                ldsm4(a[mi][0], a[mi][1], a[mi][2], a[mi][3], addr);          \
            }                                                                 \
            _Pragma("unroll") for (int jp = 0; jp < 2; jp++) {                \
                uint32_t addr = bbase + ((brow + jp * 16) * LDB + k0 + bcoff) * 4; \
                uint32_t r0, r1, r2, r3;                                      \
                ldsm4(r0, r1, r2, r3, addr);                                  \
                b[jp * 2][0] = r0; b[jp * 2][1] = r1;                         \
                b[jp * 2 + 1][0] = r2; b[jp * 2 + 1][1] = r3;                 \
            }                                                                 \
            _Pragma("unroll") for (int mi = 0; mi < 2; mi++)                  \
                _Pragma("unroll") for (int nj = 0; nj < 4; nj++)              \
                    mma_tf32(c[mi][nj], a[mi], b[nj]);                        \
        }                                                                     \
    } while (0)

    GEMM_LDG(kbeg);
    GEMM_STS(0);
    __syncthreads();

    for (int it = 0; it < NIT; ++it) {
        if (it + 1 < NIT) GEMM_LDG(kbeg + (it + 1) * BK);
        GEMM_COMPUTE(it & 1);
        __syncthreads();
        if (it + 1 < NIT) GEMM_STS((it + 1) & 1);
        __syncthreads();
    }

    float *Cout = C + (size_t)blockIdx.y * NNODES * HDIM;
    int crow = m0 + wm * 32 + (lane >> 2);
    int ccol = wn * 32 + (lane & 3) * 2;
#pragma unroll
    for (int mi = 0; mi < 2; mi++)
#pragma unroll
        for (int nj = 0; nj < 4; nj++) {
            int r = crow + mi * 16, cl = ccol + nj * 8;
            *(float2 *)(Cout + (size_t)r * HDIM + cl) =
                make_float2(c[mi][nj][0], c[mi][nj][1]);
            *(float2 *)(Cout + (size_t)(r + 8) * HDIM + cl) =
                make_float2(c[mi][nj][2], c[mi][nj][3]);
        }
#undef GEMM_LDG
#undef GEMM_STS
#undef GEMM_COMPUTE
}

// ---------------------------------------------------------------------------
// mid: h0 = LN(relu(ZP0+ZP1+b0); g0,be0); store h0; Y1T = round_tf32((h0@W1)^T)
// block (32,8), one warp per row
// ---------------------------------------------------------------------------
__global__ void mid_kernel(const float *__restrict__ b0, const float *__restrict__ g0,
                           const float *__restrict__ be0, const float *__restrict__ W1) {
    __shared__ float W1s[HDIM][HDIM];
    __shared__ float hrow[8][HDIM];
    int lane = threadIdx.x, ty = threadIdx.y;
    int tid = ty * 32 + lane;
#pragma unroll
    for (int j = 0; j < 16; j++) {
        int idx = tid + 256 * j;  // 4096
        W1s[idx >> 6][idx & 63] = W1[idx];
    }
    __syncthreads();

    int row = blockIdx.x * 8 + ty;
    const float *zp0 = dZP + (size_t)row * HDIM;
    const float *zp1 = dZP + (size_t)NNODES * HDIM + (size_t)row * HDIM;
    float z0 = fmaxf(zp0[lane] + zp1[lane] + b0[lane], 0.f);
    float z1 = fmaxf(zp0[lane + 32] + zp1[lane + 32] + b0[lane + 32], 0.f);
    float s = z0 + z1;
#pragma unroll
    for (int o = 16; o > 0; o >>= 1) s += __shfl_xor_sync(0xffffffffu, s, o);
    float m = s * (1.f / 64.f);
    float d0 = z0 - m, d1 = z1 - m;
    float v = d0 * d0 + d1 * d1;
#pragma unroll
    for (int o = 16; o > 0; o >>= 1) v += __shfl_xor_sync(0xffffffffu, v, o);
    float rs = rsqrtf(v * (1.f / 64.f) + LNEPS);
    float h0a = d0 * rs * g0[lane] + be0[lane];
    float h0b = d1 * rs * g0[lane + 32] + be0[lane + 32];
    dH0[(size_t)row * HDIM + lane] = h0a;
    dH0[(size_t)row * HDIM + lane + 32] = h0b;
    hrow[ty][lane] = h0a;
    hrow[ty][lane + 32] = h0b;
    __syncwarp();
    float a0 = 0.f, a1 = 0.f;
#pragma unroll
    for (int j = 0; j < HDIM; j++) {
        float hj = hrow[ty][j];
        a0 += hj * W1s[j][lane];
        a1 += hj * W1s[j][lane + 32];
    }
    dY1T[(size_t)lane * NNODES + row] = __uint_as_float(f2tf(a0));
    dY1T[(size_t)(lane + 32) * NNODES + row] = __uint_as_float(f2tf(a1));
}

// ---------------------------------------------------------------------------
// epi2: h = LN(relu(ZP0+ZP1+b1); g1,be1) + h0; feat/attn matvecs; segment atomics
// ---------------------------------------------------------------------------
__global__ void epi2_kernel(const int *__restrict__ I, const float *__restrict__ b1,
                            const float *__restrict__ g1, const float *__restrict__ be1,
                            const float *__restrict__ Wf, const float *__restrict__ bf,
                            const float *__restrict__ Wa, const float *__restrict__ ba) {
    __shared__ float Wfs[HDIM][HDIM];
    __shared__ float Was[HDIM][HDIM];
    __shared__ float hrow[8][HDIM];
    int lane = threadIdx.x, ty = threadIdx.y;
    int tid = ty * 32 + lane;
#pragma unroll
    for (int j = 0; j < 16; j++) {
        int idx = tid + 256 * j;
        Wfs[idx >> 6][idx & 63] = Wf[idx];
        Was[idx >> 6][idx & 63] = Wa[idx];
    }
    __syncthreads();

    int row = blockIdx.x * 8 + ty;
    const float *zp0 = dZP + (size_t)row * HDIM;
    const float *zp1 = dZP + (size_t)NNODES * HDIM + (size_t)row * HDIM;
    float z0 = fmaxf(zp0[lane] + zp1[lane] + b1[lane], 0.f);
    float z1 = fmaxf(zp0[lane + 32] + zp1[lane + 32] + b1[lane + 32], 0.f);
    float s = z0 + z1;
#pragma unroll
    for (int o = 16; o > 0; o >>= 1) s += __shfl_xor_sync(0xffffffffu, s, o);
    float m = s * (1.f / 64.f);
    float d0 = z0 - m, d1 = z1 - m;
    float v = d0 * d0 + d1 * d1;
#pragma unroll
    for (int o = 16; o > 0; o >>= 1) v += __shfl_xor_sync(0xffffffffu, v, o);
    float rs = rsqrtf(v * (1.f / 64.f) + LNEPS);
    float ha = d0 * rs * g1[lane] + be1[lane] + dH0[(size_t)row * HDIM + lane];
    float hb = d1 * rs * g1[lane + 32] + be1[lane + 32] + dH0[(size_t)row * HDIM + lane + 32];
    hrow[ty][lane] = ha;
    hrow[ty][lane + 32] = hb;
    __syncwarp();

    float f0 = bf[lane], f1 = bf[lane + 32];
    float t0 = ba[lane], t1 = ba[lane + 32];
#pragma unroll
    for (int j = 0; j < HDIM; j++) {
        float hj = hrow[ty][j];
        f0 += hj * Wfs[j][lane];
        f1 += hj * Wfs[j][lane + 32];
        t0 += hj * Was[j][lane];
        t1 += hj * Was[j][lane + 32];
    }
    t0 = 1.f / (1.f + expf(-t0));
    t1 = 1.f / (1.f + expf(-t1));
    int g = I[row];
    atomicAdd(&dG[g * HDIM + lane], f0 * t0);
    atomicAdd(&dG[g * HDIM + lane + 32], f1 * t1);
}

// ---------------------------------------------------------------------------
// final: out[g] = [Gacc[g] | bary[g]] @ Wout + bout
// ---------------------------------------------------------------------------
__global__ void final_kernel(const float *__restrict__ Wout,
                             const float *__restrict__ bout, float *__restrict__ out) {
    int g = blockIdx.x * 64 + threadIdx.x;
    if (g >= GSEG) return;
    float a0 = bout[0], a1 = bout[1], a2 = bout[2];
#pragma unroll
    for (int j = 0; j < HDIM; j++) {
        float v = dG[g * HDIM + j];
        a0 += v * Wout[j * 3 + 0];
        a1 += v * Wout[j * 3 + 1];
        a2 += v * Wout[j * 3 + 2];
    }
    float zs = dZsum[g];
    float inv = zs > 0.f ? 1.f / zs : 0.f;
#pragma unroll
    for (int d = 0; d < 3; d++) {
        float b = dZnum[g * 3 + d] * inv;
        a0 += b * Wout[(HDIM + d) * 3 + 0];
        a1 += b * Wout[(HDIM + d) * 3 + 1];
        a2 += b * Wout[(HDIM + d) * 3 + 2];
    }
    out[g * 3 + 0] = a0;
    out[g * 3 + 1] = a1;
    out[g * 3 + 2] = a2;
}

// ---------------------------------------------------------------------------
// launch
// ---------------------------------------------------------------------------
extern "C" void kernel_launch(void *const *d_in, const int *in_sizes, int n_in,
                              void *d_out, int out_size) {
    const float *X = (const float *)d_in[0];
    const float *A = (const float *)d_in[1];
    const int *I = (const int *)d_in[2];
    const float *W0 = (const float *)d_in[3];
    const float *b0 = (const float *)d_in[4];
    const float *g0 = (const float *)d_in[5];
    const float *be0 = (const float *)d_in[6];
    const float *W1 = (const float *)d_in[7];
    const float *b1 = (const float *)d_in[8];
    const float *g1 = (const float *)d_in[9];
    const float *be1 = (const float *)d_in[10];
    const float *Wf = (const float *)d_in[11];
    const float *bf = (const float *)d_in[12];
    const float *Wa = (const float *)d_in[13];
    const float *ba = (const float *)d_in[14];
    const float *Wout = (const float *)d_in[15];
    const float *bout = (const float *)d_in[16];
    float *out = (float *)d_out;

    float *y0t, *zp, *y1t;
    cudaGetSymbolAddress((void **)&y0t, dY0T);
    cudaGetSymbolAddress((void **)&zp, dZP);
    cudaGetSymbolAddress((void **)&y1t, dY1T);

    const int smem_bytes = (2 * BM * LDA + 2 * 64 * LDB) * 4;  // 55296
    cudaFuncSetAttribute(gemm_tf32, cudaFuncAttributeMaxDynamicSharedMemorySize,
                         smem_bytes);

    init_kernel<<<64, 256>>>();
    zmax_kernel<<<NNODES / 256, 256>>>(X, I);
    zexp_kernel<<<NNODES / 256, 256>>>(X, I);
    y0t_kernel<<<NNODES / 8, dim3(32, 8)>>>(X, W0);
    gemm_tf32<<<dim3(NNODES / BM, 2), 256, smem_bytes>>>(A, y0t, zp);
    mid_kernel<<<NNODES / 8, dim3(32, 8)>>>(b0, g0, be0, W1);
    gemm_tf32<<<dim3(NNODES / BM, 2), 256, smem_bytes>>>(A, y1t, zp);
    epi2_kernel<<<NNODES / 8, dim3(32, 8)>>>(I, b1, g1, be1, Wf, bf, Wa, ba);
    final_kernel<<<(GSEG + 63) / 64, 64>>>(Wout, bout, out);
}

// round 2
// speedup vs baseline: 1.4428x; 1.4428x over previous
#include <cuda_runtime.h>
#include <cuda_bf16.h>
#include <cstdint>
#include <math.h>

// ---------------------------------------------------------------------------
// Problem constants
// ---------------------------------------------------------------------------
#define NNODES 8192
#define FDIM   16
#define HDIM   64
#define GSEG   256
#define LNEPS  1e-3f

// GEMM tiling
#define BM 128
#define BK 32
#define KSPLIT 4096          // split-K = 2
#define LDA 36               // smem row pitch (floats) for A tiles
#define LDB 36               // smem row pitch (floats) for B tiles
#define NIT (KSPLIT / BK)    // 128 k-iterations per CTA
#define NSTAGE 5             // cp.async pipeline depth

// ---------------------------------------------------------------------------
// Device scratch (no allocations allowed)
// ---------------------------------------------------------------------------
__device__ float dY0T[HDIM * NNODES];      // (X@W0)^T, tf32-rounded
__device__ float dZP[2 * NNODES * HDIM];   // split-K partials of A@Y
__device__ float dH0[NNODES * HDIM];       // layer-0 hidden
__device__ float dY1T[HDIM * NNODES];      // (h0@W1)^T, tf32-rounded
__device__ float dG[GSEG * HDIM];          // attention-pool accumulator
__device__ float dZmax[GSEG];
__device__ float dZsum[GSEG];
__device__ float dZnum[GSEG * 3];

// ---------------------------------------------------------------------------
// Small PTX helpers
// ---------------------------------------------------------------------------
__device__ __forceinline__ uint32_t f2tf(float x) {
    uint32_t r;
    asm("cvt.rna.tf32.f32 %0, %1;" : "=r"(r) : "f"(x));
    return r;
}

__device__ __forceinline__ uint32_t f2tf_bits(uint32_t x) {
    uint32_t r;
    asm("cvt.rna.tf32.f32 %0, %1;" : "=r"(r) : "f"(__uint_as_float(x)));
    return r;
}

__device__ __forceinline__ void cpa16(uint32_t dst, const void *src) {
    asm volatile("cp.async.cg.shared.global [%0], [%1], 16;" ::"r"(dst), "l"(src));
}

__device__ __forceinline__ void cpa_commit() {
    asm volatile("cp.async.commit_group;");
}

__device__ __forceinline__ void cpa_wait3() {
    asm volatile("cp.async.wait_group 3;");   // NSTAGE-2
}

__device__ __forceinline__ void ldsm4(uint32_t &r0, uint32_t &r1, uint32_t &r2,
                                      uint32_t &r3, uint32_t addr) {
    asm volatile("ldmatrix.sync.aligned.m8n8.x4.shared.b16 {%0,%1,%2,%3}, [%4];"
                 : "=r"(r0), "=r"(r1), "=r"(r2), "=r"(r3) : "r"(addr));
}

__device__ __forceinline__ void mma_tf32(float c[4], const uint32_t a[4],
                                         const uint32_t b[2]) {
    asm volatile(
        "mma.sync.aligned.m16n8k8.row.col.f32.tf32.tf32.f32 "
        "{%0,%1,%2,%3}, {%4,%5,%6,%7}, {%8,%9}, {%0,%1,%2,%3};"
        : "+f"(c[0]), "+f"(c[1]), "+f"(c[2]), "+f"(c[3])
        : "r"(a[0]), "r"(a[1]), "r"(a[2]), "r"(a[3]), "r"(b[0]), "r"(b[1]));
}

// ---------------------------------------------------------------------------
// init: zero accumulators
// ---------------------------------------------------------------------------
__global__ void init_kernel() {
    int i = blockIdx.x * 256 + threadIdx.x;
    if (i < GSEG * HDIM) dG[i] = 0.f;
    if (i < GSEG) { dZmax[i] = 0.f; dZsum[i] = 0.f; }
    if (i < GSEG * 3) dZnum[i] = 0.f;
}

// ---------------------------------------------------------------------------
// segment max of z = log1p(relu(X[:,0]))  (z >= 0, so int-compare atomicMax ok)
// ---------------------------------------------------------------------------
__global__ void zmax_kernel(const float *__restrict__ X, const int *__restrict__ I) {
    int i = blockIdx.x * 256 + threadIdx.x;
    if (i >= NNODES) return;
    float z = log1pf(fmaxf(X[i * FDIM], 0.f));
    atomicMax((int *)&dZmax[I[i]], __float_as_int(z));
}

// zexp sums + xyz-weighted sums
__global__ void zexp_kernel(const float *__restrict__ X, const int *__restrict__ I) {
    int i = blockIdx.x * 256 + threadIdx.x;
    if (i >= NNODES) return;
    float z = log1pf(fmaxf(X[i * FDIM], 0.f));
    int g = I[i];
    float w = expf(z - dZmax[g]);
    atomicAdd(&dZsum[g], w);
    atomicAdd(&dZnum[g * 3 + 0], w * X[i * FDIM + 13]);
    atomicAdd(&dZnum[g * 3 + 1], w * X[i * FDIM + 14]);
    atomicAdd(&dZnum[g * 3 + 2], w * X[i * FDIM + 15]);
}

// ---------------------------------------------------------------------------
// Y0T[n][i] = round_tf32( sum_f X[i][f] * W0[f][n] )
// ---------------------------------------------------------------------------
__global__ void y0t_kernel(const float *__restrict__ X, const float *__restrict__ W0) {
    __shared__ float W0s[FDIM][HDIM];
    int lane = threadIdx.x, ty = threadIdx.y;
    int tid = ty * 32 + lane;
#pragma unroll
    for (int j = 0; j < 4; j++) {
        int idx = tid + 256 * j;  // 1024 = 16*64
        W0s[idx >> 6][idx & 63] = W0[idx];
    }
    __syncthreads();
    int row = blockIdx.x * 8 + ty;
    float a0 = 0.f, a1 = 0.f;
#pragma unroll
    for (int f = 0; f < FDIM; f++) {
        float xf = X[row * FDIM + f];
        a0 += xf * W0s[f][lane];
        a1 += xf * W0s[f][lane + 32];
    }
    dY0T[(size_t)lane * NNODES + row] = __uint_as_float(f2tf(a0));
    dY0T[(size_t)(lane + 32) * NNODES + row] = __uint_as_float(f2tf(a1));
}

// ---------------------------------------------------------------------------
// tf32 tensor-core GEMM with 5-stage cp.async pipeline
//   C_partial[blockIdx.y] = A[:, y*4096:(y+1)*4096] @ BT^T
// ---------------------------------------------------------------------------
__global__ void __launch_bounds__(256, 1)
gemm_tf32(const float *__restrict__ A, const float *__restrict__ BT,
          float *__restrict__ C) {
    extern __shared__ float smem[];
    float *As = smem;                        // [NSTAGE][BM][LDA]
    float *Bs = smem + NSTAGE * BM * LDA;    // [NSTAGE][64][LDB]

    const int tid = threadIdx.x;
    const int lane = tid & 31, wid = tid >> 5;
    const int wm = wid & 3, wn = wid >> 2;   // 4 m-warps x 2 n-warps
    const int m0 = blockIdx.x * BM;
    const int kbeg = blockIdx.y * KSPLIT;

    float c[2][4][4] = {};

    // per-thread load coordinates (row = idx>>3, 4-col group = idx&7)
    const int lr = tid >> 3;       // 0..31
    const int lc = (tid & 7) * 4;  // 0,4,...,28
    const float *gA = A + (size_t)(m0 + lr) * NNODES + kbeg + lc;
    const float *gB = BT + (size_t)lr * NNODES + kbeg + lc;  // rows 0..31 (j adds 32)
    const uint32_t sA = (uint32_t)__cvta_generic_to_shared(As) + (lr * LDA + lc) * 4;
    const uint32_t sB = (uint32_t)__cvta_generic_to_shared(Bs) + (lr * LDB + lc) * 4;

    // ldmatrix lane-derived offsets
    const int arow = wm * 32 + (lane & 7) + ((lane >> 3) & 1) * 8;
    const int acoff = ((lane >> 4) & 1) * 4;
    const int brow = wn * 32 + (lane & 7) + ((lane >> 4) & 1) * 8;
    const int bcoff = ((lane >> 3) & 1) * 4;

#define GEMM_ISSUE(IT)                                                        \
    do {                                                                      \
        int buf = (IT) % NSTAGE;                                              \
        size_t koff = (size_t)(IT) * BK;                                      \
        uint32_t da = sA + buf * (BM * LDA * 4);                              \
        uint32_t db = sB + buf * (64 * LDB * 4);                              \
        _Pragma("unroll") for (int j = 0; j < 4; j++)                         \
            cpa16(da + j * (32 * LDA * 4), gA + koff + (size_t)j * 32 * NNODES); \
        _Pragma("unroll") for (int j = 0; j < 2; j++)                         \
            cpa16(db + j * (32 * LDB * 4), gB + koff + (size_t)j * 32 * NNODES); \
    } while (0)

#define GEMM_COMPUTE(BUF)                                                     \
    do {                                                                      \
        uint32_t abase = (uint32_t)__cvta_generic_to_shared(As + (BUF) * BM * LDA); \
        uint32_t bbase = (uint32_t)__cvta_generic_to_shared(Bs + (BUF) * 64 * LDB); \
        _Pragma("unroll") for (int ks = 0; ks < 4; ks++) {                    \
            int k0 = ks * 8;                                                  \
            uint32_t a[2][4], b[4][2];                                        \
            _Pragma("unroll") for (int mi = 0; mi < 2; mi++) {                \
                uint32_t addr = abase + ((arow + mi * 16) * LDA + k0 + acoff) * 4; \
                ldsm4(a[mi][0], a[mi][1], a[mi][2], a[mi][3], addr);          \
                _Pragma("unroll") for (int t = 0; t < 4; t++)                 \
                    a[mi][t] = f2tf_bits(a[mi][t]);                           \
            }                                                                 \
            _Pragma("unroll") for (int jp = 0; jp < 2; jp++) {                \
                uint32_t addr = bbase + ((brow + jp * 16) * LDB + k0 + bcoff) * 4; \
                uint32_t r0, r1, r2, r3;                                      \
                ldsm4(r0, r1, r2, r3, addr);                                  \
                b[jp * 2][0] = r0; b[jp * 2][1] = r1;                         \
                b[jp * 2 + 1][0] = r2; b[jp * 2 + 1][1] = r3;                 \
            }                                                                 \
            _Pragma("unroll") for (int mi = 0; mi < 2; mi++)                  \
                _Pragma("unroll") for (int nj = 0; nj < 4; nj++)              \
                    mma_tf32(c[mi][nj], a[mi], b[nj]);                        \
        }                                                                     \
    } while (0)

    // prologue: fill NSTAGE-1 stages
#pragma unroll
    for (int s = 0; s < NSTAGE - 1; s++) {
        GEMM_ISSUE(s);
        cpa_commit();
    }

    for (int it = 0; it < NIT; ++it) {
        cpa_wait3();
        __syncthreads();
        if (it + NSTAGE - 1 < NIT) GEMM_ISSUE(it + NSTAGE - 1);
        cpa_commit();
        GEMM_COMPUTE(it % NSTAGE);
    }

    float *Cout = C + (size_t)blockIdx.y * NNODES * HDIM;
    int crow = m0 + wm * 32 + (lane >> 2);
    int ccol = wn * 32 + (lane & 3) * 2;
#pragma unroll
    for (int mi = 0; mi < 2; mi++)
#pragma unroll
        for (int nj = 0; nj < 4; nj++) {
            int r = crow + mi * 16, cl = ccol + nj * 8;
            *(float2 *)(Cout + (size_t)r * HDIM + cl) =
                make_float2(c[mi][nj][0], c[mi][nj][1]);
            *(float2 *)(Cout + (size_t)(r + 8) * HDIM + cl) =
                make_float2(c[mi][nj][2], c[mi][nj][3]);
        }
#undef GEMM_ISSUE
#undef GEMM_COMPUTE
}

// ---------------------------------------------------------------------------
// mid: h0 = LN(relu(ZP0+ZP1+b0); g0,be0); store h0; Y1T = round_tf32((h0@W1)^T)
// ---------------------------------------------------------------------------
__global__ void mid_kernel(const float *__restrict__ b0, const float *__restrict__ g0,
                           const float *__restrict__ be0, const float *__restrict__ W1) {
    __shared__ float W1s[HDIM][HDIM];
    __shared__ float hrow[8][HDIM];
    int lane = threadIdx.x, ty = threadIdx.y;
    int tid = ty * 32 + lane;
#pragma unroll
    for (int j = 0; j < 16; j++) {
        int idx = tid + 256 * j;  // 4096
        W1s[idx >> 6][idx & 63] = W1[idx];
    }
    __syncthreads();

    int row = blockIdx.x * 8 + ty;
    const float *zp0 = dZP + (size_t)row * HDIM;
    const float *zp1 = dZP + (size_t)NNODES * HDIM + (size_t)row * HDIM;
    float z0 = fmaxf(zp0[lane] + zp1[lane] + b0[lane], 0.f);
    float z1 = fmaxf(zp0[lane + 32] + zp1[lane + 32] + b0[lane + 32], 0.f);
    float s = z0 + z1;
#pragma unroll
    for (int o = 16; o > 0; o >>= 1) s += __shfl_xor_sync(0xffffffffu, s, o);
    float m = s * (1.f / 64.f);
    float d0 = z0 - m, d1 = z1 - m;
    float v = d0 * d0 + d1 * d1;
#pragma unroll
    for (int o = 16; o > 0; o >>= 1) v += __shfl_xor_sync(0xffffffffu, v, o);
    float rs = rsqrtf(v * (1.f / 64.f) + LNEPS);
    float h0a = d0 * rs * g0[lane] + be0[lane];
    float h0b = d1 * rs * g0[lane + 32] + be0[lane + 32];
    dH0[(size_t)row * HDIM + lane] = h0a;
    dH0[(size_t)row * HDIM + lane + 32] = h0b;
    hrow[ty][lane] = h0a;
    hrow[ty][lane + 32] = h0b;
    __syncwarp();
    float a0 = 0.f, a1 = 0.f;
#pragma unroll
    for (int j = 0; j < HDIM; j++) {
        float hj = hrow[ty][j];
        a0 += hj * W1s[j][lane];
        a1 += hj * W1s[j][lane + 32];
    }
    dY1T[(size_t)lane * NNODES + row] = __uint_as_float(f2tf(a0));
    dY1T[(size_t)(lane + 32) * NNODES + row] = __uint_as_float(f2tf(a1));
}

// ---------------------------------------------------------------------------
// epi2: h = LN(relu(ZP0+ZP1+b1); g1,be1) + h0; feat/attn matvecs; segment atomics
// ---------------------------------------------------------------------------
__global__ void epi2_kernel(const int *__restrict__ I, const float *__restrict__ b1,
                            const float *__restrict__ g1, const float *__restrict__ be1,
                            const float *__restrict__ Wf, const float *__restrict__ bf,
                            const float *__restrict__ Wa, const float *__restrict__ ba) {
    __shared__ float Wfs[HDIM][HDIM];
    __shared__ float Was[HDIM][HDIM];
    __shared__ float hrow[8][HDIM];
    int lane = threadIdx.x, ty = threadIdx.y;
    int tid = ty * 32 + lane;
#pragma unroll
    for (int j = 0; j < 16; j++) {
        int idx = tid + 256 * j;
        Wfs[idx >> 6][idx & 63] = Wf[idx];
        Was[idx >> 6][idx & 63] = Wa[idx];
    }
    __syncthreads();

    int row = blockIdx.x * 8 + ty;
    const float *zp0 = dZP + (size_t)row * HDIM;
    const float *zp1 = dZP + (size_t)NNODES * HDIM + (size_t)row * HDIM;
    float z0 = fmaxf(zp0[lane] + zp1[lane] + b1[lane], 0.f);
    float z1 = fmaxf(zp0[lane + 32] + zp1[lane + 32] + b1[lane + 32], 0.f);
    float s = z0 + z1;
#pragma unroll
    for (int o = 16; o > 0; o >>= 1) s += __shfl_xor_sync(0xffffffffu, s, o);
    float m = s * (1.f / 64.f);
    float d0 = z0 - m, d1 = z1 - m;
    float v = d0 * d0 + d1 * d1;
#pragma unroll
    for (int o = 16; o > 0; o >>= 1) v += __shfl_xor_sync(0xffffffffu, v, o);
    float rs = rsqrtf(v * (1.f / 64.f) + LNEPS);
    float ha = d0 * rs * g1[lane] + be1[lane] + dH0[(size_t)row * HDIM + lane];
    float hb = d1 * rs * g1[lane + 32] + be1[lane + 32] + dH0[(size_t)row * HDIM + lane + 32];
    hrow[ty][lane] = ha;
    hrow[ty][lane + 32] = hb;
    __syncwarp();

    float f0 = bf[lane], f1 = bf[lane + 32];
    float t0 = ba[lane], t1 = ba[lane + 32];
#pragma unroll
    for (int j = 0; j < HDIM; j++) {
        float hj = hrow[ty][j];
        f0 += hj * Wfs[j][lane];
        f1 += hj * Wfs[j][lane + 32];
        t0 += hj * Was[j][lane];
        t1 += hj * Was[j][lane + 32];
    }
    t0 = 1.f / (1.f + expf(-t0));
    t1 = 1.f / (1.f + expf(-t1));
    int g = I[row];
    atomicAdd(&dG[g * HDIM + lane], f0 * t0);
    atomicAdd(&dG[g * HDIM + lane + 32], f1 * t1);
}

// ---------------------------------------------------------------------------
// final: out[g] = [Gacc[g] | bary[g]] @ Wout + bout
// ---------------------------------------------------------------------------
__global__ void final_kernel(const float *__restrict__ Wout,
                             const float *__restrict__ bout, float *__restrict__ out) {
    int g = blockIdx.x * 64 + threadIdx.x;
    if (g >= GSEG) return;
    float a0 = bout[0], a1 = bout[1], a2 = bout[2];
#pragma unroll
    for (int j = 0; j < HDIM; j++) {
        float v = dG[g * HDIM + j];
        a0 += v * Wout[j * 3 + 0];
        a1 += v * Wout[j * 3 + 1];
        a2 += v * Wout[j * 3 + 2];
    }
    float zs = dZsum[g];
    float inv = zs > 0.f ? 1.f / zs : 0.f;
#pragma unroll
    for (int d = 0; d < 3; d++) {
        float b = dZnum[g * 3 + d] * inv;
        a0 += b * Wout[(HDIM + d) * 3 + 0];
        a1 += b * Wout[(HDIM + d) * 3 + 1];
        a2 += b * Wout[(HDIM + d) * 3 + 2];
    }
    out[g * 3 + 0] = a0;
    out[g * 3 + 1] = a1;
    out[g * 3 + 2] = a2;
}

// ---------------------------------------------------------------------------
// launch
// ---------------------------------------------------------------------------
extern "C" void kernel_launch(void *const *d_in, const int *in_sizes, int n_in,
                              void *d_out, int out_size) {
    const float *X = (const float *)d_in[0];
    const float *A = (const float *)d_in[1];
    const int *I = (const int *)d_in[2];
    const float *W0 = (const float *)d_in[3];
    const float *b0 = (const float *)d_in[4];
    const float *g0 = (const float *)d_in[5];
    const float *be0 = (const float *)d_in[6];
    const float *W1 = (const float *)d_in[7];
    const float *b1 = (const float *)d_in[8];
    const float *g1 = (const float *)d_in[9];
    const float *be1 = (const float *)d_in[10];
    const float *Wf = (const float *)d_in[11];
    const float *bf = (const float *)d_in[12];
    const float *Wa = (const float *)d_in[13];
    const float *ba = (const float *)d_in[14];
    const float *Wout = (const float *)d_in[15];
    const float *bout = (const float *)d_in[16];
    float *out = (float *)d_out;

    float *y0t, *zp, *y1t;
    cudaGetSymbolAddress((void **)&y0t, dY0T);
    cudaGetSymbolAddress((void **)&zp, dZP);
    cudaGetSymbolAddress((void **)&y1t, dY1T);

    const int smem_bytes = NSTAGE * (BM * LDA + 64 * LDB) * 4;  // 138240
    cudaFuncSetAttribute(gemm_tf32, cudaFuncAttributeMaxDynamicSharedMemorySize,
                         smem_bytes);

    init_kernel<<<64, 256>>>();
    zmax_kernel<<<NNODES / 256, 256>>>(X, I);
    zexp_kernel<<<NNODES / 256, 256>>>(X, I);
    y0t_kernel<<<NNODES / 8, dim3(32, 8)>>>(X, W0);
    gemm_tf32<<<dim3(NNODES / BM, 2), 256, smem_bytes>>>(A, y0t, zp);
    mid_kernel<<<NNODES / 8, dim3(32, 8)>>>(b0, g0, be0, W1);
    gemm_tf32<<<dim3(NNODES / BM, 2), 256, smem_bytes>>>(A, y1t, zp);
    epi2_kernel<<<NNODES / 8, dim3(32, 8)>>>(I, b1, g1, be1, Wf, bf, Wa, ba);
    final_kernel<<<(GSEG + 63) / 64, 64>>>(Wout, bout, out);
}

// round 4
// speedup vs baseline: 1.6962x; 1.1757x over previous
#include <cuda_runtime.h>
#include <cuda_bf16.h>
#include <cstdint>
#include <math.h>

// ---------------------------------------------------------------------------
// Problem constants
// ---------------------------------------------------------------------------
#define NNODES 8192
#define FDIM   16
#define HDIM   64
#define GSEG   256
#define LNEPS  1e-3f

// GEMM tiling
#define BM 128
#define BK 32
#define NSPLIT 4
#define KSPLIT (NNODES / NSPLIT)   // 2048
#define LDA 36                      // smem row pitch (floats)
#define LDB 36
#define NIT (KSPLIT / BK)           // 64 k-iterations per CTA
#define NSTAGE 4                    // cp.async pipeline depth

// ---------------------------------------------------------------------------
// Device scratch (no allocations allowed)
// ---------------------------------------------------------------------------
__device__ float dY0T[HDIM * NNODES];          // (X@W0)^T, tf32-rounded
__device__ float dZP[NSPLIT * NNODES * HDIM];  // split-K partials of A@Y
__device__ float dH0[NNODES * HDIM];           // layer-0 hidden
__device__ float dY1T[HDIM * NNODES];          // (h0@W1)^T, tf32-rounded
__device__ float dG[GSEG * HDIM];              // attention-pool accumulator
__device__ float dZmax[GSEG];
__device__ float dZsum[GSEG];
__device__ float dZnum[GSEG * 3];

// ---------------------------------------------------------------------------
// Small PTX helpers
// ---------------------------------------------------------------------------
__device__ __forceinline__ uint32_t f2tf(float x) {
    uint32_t r;
    asm("cvt.rna.tf32.f32 %0, %1;" : "=r"(r) : "f"(x));
    return r;
}

__device__ __forceinline__ void cpa16(uint32_t dst, const void *src) {
    asm volatile("cp.async.cg.shared.global [%0], [%1], 16;" ::"r"(dst), "l"(src));
}

__device__ __forceinline__ void cpa_commit() {
    asm volatile("cp.async.commit_group;");
}

__device__ __forceinline__ void cpa_wait2() {
    asm volatile("cp.async.wait_group 2;");   // NSTAGE-2
}

__device__ __forceinline__ void ldsm4(uint32_t &r0, uint32_t &r1, uint32_t &r2,
                                      uint32_t &r3, uint32_t addr) {
    asm volatile("ldmatrix.sync.aligned.m8n8.x4.shared.b16 {%0,%1,%2,%3}, [%4];"
                 : "=r"(r0), "=r"(r1), "=r"(r2), "=r"(r3) : "r"(addr));
}

__device__ __forceinline__ void mma_tf32(float c[4], const uint32_t a[4],
                                         const uint32_t b[2]) {
    asm volatile(
        "mma.sync.aligned.m16n8k8.row.col.f32.tf32.tf32.f32 "
        "{%0,%1,%2,%3}, {%4,%5,%6,%7}, {%8,%9}, {%0,%1,%2,%3};"
        : "+f"(c[0]), "+f"(c[1]), "+f"(c[2]), "+f"(c[3])
        : "r"(a[0]), "r"(a[1]), "r"(a[2]), "r"(a[3]), "r"(b[0]), "r"(b[1]));
}

// ---------------------------------------------------------------------------
// init: zero accumulators
// ---------------------------------------------------------------------------
__global__ void init_kernel() {
    int i = blockIdx.x * 256 + threadIdx.x;
    if (i < GSEG * HDIM) dG[i] = 0.f;
    if (i < GSEG) { dZmax[i] = 0.f; dZsum[i] = 0.f; }
    if (i < GSEG * 3) dZnum[i] = 0.f;
}

// ---------------------------------------------------------------------------
// segment max of z = log1p(relu(X[:,0]))  (z >= 0, so int-compare atomicMax ok)
// ---------------------------------------------------------------------------
__global__ void zmax_kernel(const float *__restrict__ X, const int *__restrict__ I) {
    int i = blockIdx.x * 256 + threadIdx.x;
    if (i >= NNODES) return;
    float z = log1pf(fmaxf(X[i * FDIM], 0.f));
    atomicMax((int *)&dZmax[I[i]], __float_as_int(z));
}

// zexp sums + xyz-weighted sums
__global__ void zexp_kernel(const float *__restrict__ X, const int *__restrict__ I) {
    int i = blockIdx.x * 256 + threadIdx.x;
    if (i >= NNODES) return;
    float z = log1pf(fmaxf(X[i * FDIM], 0.f));
    int g = I[i];
    float w = expf(z - dZmax[g]);
    atomicAdd(&dZsum[g], w);
    atomicAdd(&dZnum[g * 3 + 0], w * X[i * FDIM + 13]);
    atomicAdd(&dZnum[g * 3 + 1], w * X[i * FDIM + 14]);
    atomicAdd(&dZnum[g * 3 + 2], w * X[i * FDIM + 15]);
}

// ---------------------------------------------------------------------------
// y0t: Y0T[n][i] = tf32(sum_f X[i][f]*W0[f][n]); smem-staged transposed store
// block (32,8): warp ty handles row blk*8+ty
// ---------------------------------------------------------------------------
__global__ void y0t_kernel(const float *__restrict__ X, const float *__restrict__ W0) {
    __shared__ float W0s[FDIM][HDIM];
    __shared__ float ybuf[8][68];
    int lane = threadIdx.x, ty = threadIdx.y;
    int tid = ty * 32 + lane;
#pragma unroll
    for (int j = 0; j < 4; j++) {
        int idx = tid + 256 * j;  // 1024 = 16*64
        W0s[idx >> 6][idx & 63] = W0[idx];
    }
    __syncthreads();
    int row0 = blockIdx.x * 8;
    int row = row0 + ty;
    float a0 = 0.f, a1 = 0.f;
#pragma unroll
    for (int f = 0; f < FDIM; f++) {
        float xf = X[row * FDIM + f];
        a0 += xf * W0s[f][lane];
        a1 += xf * W0s[f][lane + 32];
    }
    ybuf[ty][lane] = __uint_as_float(f2tf(a0));
    ybuf[ty][lane + 32] = __uint_as_float(f2tf(a1));
    __syncthreads();
#pragma unroll
    for (int k = 0; k < 2; k++) {
        int v = tid + 256 * k;   // 0..511
        int n = v >> 3, r = v & 7;
        dY0T[(size_t)n * NNODES + row0 + r] = ybuf[r][n];
    }
}

// ---------------------------------------------------------------------------
// tf32 tensor-core GEMM, 4-stage cp.async pipeline, 2 CTAs/SM, split-K=4
//   dZP[blockIdx.y] = A[:, y*2048:(y+1)*2048] @ BT^T
// A fragments are fed raw f32 (HW truncation to tf32); B pre-rounded RNA.
// ---------------------------------------------------------------------------
__global__ void __launch_bounds__(256, 2)
gemm_tf32(const float *__restrict__ A, const float *__restrict__ BT,
          float *__restrict__ C) {
    extern __shared__ float smem[];
    float *As = smem;                        // [NSTAGE][BM][LDA]
    float *Bs = smem + NSTAGE * BM * LDA;    // [NSTAGE][64][LDB]

    const int tid = threadIdx.x;
    const int lane = tid & 31, wid = tid >> 5;
    const int wm = wid & 3, wn = wid >> 2;   // 4 m-warps x 2 n-warps
    const int m0 = blockIdx.x * BM;
    const int kbeg = blockIdx.y * KSPLIT;

    float c[2][4][4] = {};

    // per-thread load coordinates (row = tid>>3, 4-col group = tid&7)
    const int lr = tid >> 3;       // 0..31
    const int lc = (tid & 7) * 4;  // 0,4,...,28
    const float *gA = A + (size_t)(m0 + lr) * NNODES + kbeg + lc;
    const float *gB = BT + (size_t)lr * NNODES + kbeg + lc;
    const uint32_t sA = (uint32_t)__cvta_generic_to_shared(As) + (lr * LDA + lc) * 4;
    const uint32_t sB = (uint32_t)__cvta_generic_to_shared(Bs) + (lr * LDB + lc) * 4;

    // ldmatrix lane-derived offsets
    const int arow = wm * 32 + (lane & 7) + ((lane >> 3) & 1) * 8;
    const int acoff = ((lane >> 4) & 1) * 4;
    const int brow = wn * 32 + (lane & 7) + ((lane >> 4) & 1) * 8;
    const int bcoff = ((lane >> 3) & 1) * 4;

#define GEMM_ISSUE(IT)                                                        \
    do {                                                                      \
        int buf = (IT) % NSTAGE;                                              \
        size_t koff = (size_t)(IT) * BK;                                      \
        uint32_t da = sA + buf * (BM * LDA * 4);                              \
        uint32_t db = sB + buf * (64 * LDB * 4);                              \
        _Pragma("unroll") for (int j = 0; j < 4; j++)                         \
            cpa16(da + j * (32 * LDA * 4), gA + koff + (size_t)j * 32 * NNODES); \
        _Pragma("unroll") for (int j = 0; j < 2; j++)                         \
            cpa16(db + j * (32 * LDB * 4), gB + koff + (size_t)j * 32 * NNODES); \
    } while (0)

#define GEMM_COMPUTE(BUF)                                                     \
    do {                                                                      \
        uint32_t abase = (uint32_t)__cvta_generic_to_shared(As + (BUF) * BM * LDA); \
        uint32_t bbase = (uint32_t)__cvta_generic_to_shared(Bs + (BUF) * 64 * LDB); \
        _Pragma("unroll") for (int ks = 0; ks < 4; ks++) {                    \
            int k0 = ks * 8;                                                  \
            uint32_t a[2][4], b[4][2];                                        \
            _Pragma("unroll") for (int mi = 0; mi < 2; mi++) {                \
                uint32_t addr = abase + ((arow + mi * 16) * LDA + k0 + acoff) * 4; \
                ldsm4(a[mi][0], a[mi][1], a[mi][2], a[mi][3], addr);          \
            }                                                                 \
            _Pragma("unroll") for (int jp = 0; jp < 2; jp++) {                \
                uint32_t addr = bbase + ((brow + jp * 16) * LDB + k0 + bcoff) * 4; \
                uint32_t r0, r1, r2, r3;                                      \
                ldsm4(r0, r1, r2, r3, addr);                                  \
                b[jp * 2][0] = r0; b[jp * 2][1] = r1;                         \
                b[jp * 2 + 1][0] = r2; b[jp * 2 + 1][1] = r3;                 \
            }                                                                 \
            _Pragma("unroll") for (int mi = 0; mi < 2; mi++)                  \
                _Pragma("unroll") for (int nj = 0; nj < 4; nj++)              \
                    mma_tf32(c[mi][nj], a[mi], b[nj]);                        \
        }                                                                     \
    } while (0)

    // prologue: fill NSTAGE-1 stages
#pragma unroll
    for (int s = 0; s < NSTAGE - 1; s++) {
        GEMM_ISSUE(s);
        cpa_commit();
    }

    for (int it = 0; it < NIT; ++it) {
        cpa_wait2();
        __syncthreads();
        if (it + NSTAGE - 1 < NIT) GEMM_ISSUE(it + NSTAGE - 1);
        cpa_commit();
        GEMM_COMPUTE(it % NSTAGE);
    }

    float *Cout = C + (size_t)blockIdx.y * NNODES * HDIM;
    int crow = m0 + wm * 32 + (lane >> 2);
    int ccol = wn * 32 + (lane & 3) * 2;
#pragma unroll
    for (int mi = 0; mi < 2; mi++)
#pragma unroll
        for (int nj = 0; nj < 4; nj++) {
            int r = crow + mi * 16, cl = ccol + nj * 8;
            *(float2 *)(Cout + (size_t)r * HDIM + cl) =
                make_float2(c[mi][nj][0], c[mi][nj][1]);
            *(float2 *)(Cout + (size_t)(r + 8) * HDIM + cl) =
                make_float2(c[mi][nj][2], c[mi][nj][3]);
        }
#undef GEMM_ISSUE
#undef GEMM_COMPUTE
}

// ---------------------------------------------------------------------------
// mid: h0 = LN(relu(sum ZP + b0); g0,be0); store h0; Y1T = tf32((h0@W1)^T)
// ---------------------------------------------------------------------------
__global__ void mid_kernel(const float *__restrict__ b0, const float *__restrict__ g0,
                           const float *__restrict__ be0, const float *__restrict__ W1) {
    __shared__ float W1s[HDIM][HDIM];
    __shared__ float hrow[8][HDIM];
    __shared__ float ybuf[8][68];
    int lane = threadIdx.x, ty = threadIdx.y;
    int tid = ty * 32 + lane;
#pragma unroll
    for (int j = 0; j < 16; j++) {
        int idx = tid + 256 * j;  // 4096
        W1s[idx >> 6][idx & 63] = W1[idx];
    }
    __syncthreads();

    int row0 = blockIdx.x * 8;
    int row = row0 + ty;
    float z0 = b0[lane], z1 = b0[lane + 32];
#pragma unroll
    for (int s = 0; s < NSPLIT; s++) {
        const float *zp = dZP + (size_t)s * NNODES * HDIM + (size_t)row * HDIM;
        z0 += zp[lane];
        z1 += zp[lane + 32];
    }
    z0 = fmaxf(z0, 0.f);
    z1 = fmaxf(z1, 0.f);
    float s = z0 + z1;
#pragma unroll
    for (int o = 16; o > 0; o >>= 1) s += __shfl_xor_sync(0xffffffffu, s, o);
    float m = s * (1.f / 64.f);
    float d0 = z0 - m, d1 = z1 - m;
    float v = d0 * d0 + d1 * d1;
#pragma unroll
    for (int o = 16; o > 0; o >>= 1) v += __shfl_xor_sync(0xffffffffu, v, o);
    float rs = rsqrtf(v * (1.f / 64.f) + LNEPS);
    float h0a = d0 * rs * g0[lane] + be0[lane];
    float h0b = d1 * rs * g0[lane + 32] + be0[lane + 32];
    dH0[(size_t)row * HDIM + lane] = h0a;
    dH0[(size_t)row * HDIM + lane + 32] = h0b;
    hrow[ty][lane] = h0a;
    hrow[ty][lane + 32] = h0b;
    __syncwarp();
    float a0 = 0.f, a1 = 0.f;
#pragma unroll
    for (int j = 0; j < HDIM; j++) {
        float hj = hrow[ty][j];
        a0 += hj * W1s[j][lane];
        a1 += hj * W1s[j][lane + 32];
    }
    ybuf[ty][lane] = __uint_as_float(f2tf(a0));
    ybuf[ty][lane + 32] = __uint_as_float(f2tf(a1));
    __syncthreads();
#pragma unroll
    for (int k = 0; k < 2; k++) {
        int vv = tid + 256 * k;
        int n = vv >> 3, r = vv & 7;
        dY1T[(size_t)n * NNODES + row0 + r] = ybuf[r][n];
    }
}

// ---------------------------------------------------------------------------
// epi2: h = LN(relu(sum ZP + b1); g1,be1) + h0; feat/attn matvecs; seg atomics
// ---------------------------------------------------------------------------
__global__ void epi2_kernel(const int *__restrict__ I, const float *__restrict__ b1,
                            const float *__restrict__ g1, const float *__restrict__ be1,
                            const float *__restrict__ Wf, const float *__restrict__ bf,
                            const float *__restrict__ Wa, const float *__restrict__ ba) {
    __shared__ float Wfs[HDIM][HDIM];
    __shared__ float Was[HDIM][HDIM];
    __shared__ float hrow[8][HDIM];
    int lane = threadIdx.x, ty = threadIdx.y;
    int tid = ty * 32 + lane;
#pragma unroll
    for (int j = 0; j < 16; j++) {
        int idx = tid + 256 * j;
        Wfs[idx >> 6][idx & 63] = Wf[idx];
        Was[idx >> 6][idx & 63] = Wa[idx];
    }
    __syncthreads();

    int row = blockIdx.x * 8 + ty;
    float z0 = b1[lane], z1 = b1[lane + 32];
#pragma unroll
    for (int s = 0; s < NSPLIT; s++) {
        const float *zp = dZP + (size_t)s * NNODES * HDIM + (size_t)row * HDIM;
        z0 += zp[lane];
        z1 += zp[lane + 32];
    }
    z0 = fmaxf(z0, 0.f);
    z1 = fmaxf(z1, 0.f);
    float s = z0 + z1;
#pragma unroll
    for (int o = 16; o > 0; o >>= 1) s += __shfl_xor_sync(0xffffffffu, s, o);
    float m = s * (1.f / 64.f);
    float d0 = z0 - m, d1 = z1 - m;
    float v = d0 * d0 + d1 * d1;
#pragma unroll
    for (int o = 16; o > 0; o >>= 1) v += __shfl_xor_sync(0xffffffffu, v, o);
    float rs = rsqrtf(v * (1.f / 64.f) + LNEPS);
    float ha = d0 * rs * g1[lane] + be1[lane] + dH0[(size_t)row * HDIM + lane];
    float hb = d1 * rs * g1[lane + 32] + be1[lane + 32] + dH0[(size_t)row * HDIM + lane + 32];
    hrow[ty][lane] = ha;
    hrow[ty][lane + 32] = hb;
    __syncwarp();

    float f0 = bf[lane], f1 = bf[lane + 32];
    float t0 = ba[lane], t1 = ba[lane + 32];
#pragma unroll
    for (int j = 0; j < HDIM; j++) {
        float hj = hrow[ty][j];
        f0 += hj * Wfs[j][lane];
        f1 += hj * Wfs[j][lane + 32];
        t0 += hj * Was[j][lane];
        t1 += hj * Was[j][lane + 32];
    }
    t0 = 1.f / (1.f + expf(-t0));
    t1 = 1.f / (1.f + expf(-t1));
    int g = I[row];
    atomicAdd(&dG[g * HDIM + lane], f0 * t0);
    atomicAdd(&dG[g * HDIM + lane + 32], f1 * t1);
}

// ---------------------------------------------------------------------------
// final: out[g] = [Gacc[g] | bary[g]] @ Wout + bout
// ---------------------------------------------------------------------------
__global__ void final_kernel(const float *__restrict__ Wout,
                             const float *__restrict__ bout, float *__restrict__ out) {
    int g = blockIdx.x * 64 + threadIdx.x;
    if (g >= GSEG) return;
    float a0 = bout[0], a1 = bout[1], a2 = bout[2];
#pragma unroll
    for (int j = 0; j < HDIM; j++) {
        float v = dG[g * HDIM + j];
        a0 += v * Wout[j * 3 + 0];
        a1 += v * Wout[j * 3 + 1];
        a2 += v * Wout[j * 3 + 2];
    }
    float zs = dZsum[g];
    float inv = zs > 0.f ? 1.f / zs : 0.f;
#pragma unroll
    for (int d = 0; d < 3; d++) {
        float b = dZnum[g * 3 + d] * inv;
        a0 += b * Wout[(HDIM + d) * 3 + 0];
        a1 += b * Wout[(HDIM + d) * 3 + 1];
        a2 += b * Wout[(HDIM + d) * 3 + 2];
    }
    out[g * 3 + 0] = a0;
    out[g * 3 + 1] = a1;
    out[g * 3 + 2] = a2;
}

// ---------------------------------------------------------------------------
// launch
// ---------------------------------------------------------------------------
extern "C" void kernel_launch(void *const *d_in, const int *in_sizes, int n_in,
                              void *d_out, int out_size) {
    const float *X = (const float *)d_in[0];
    const float *A = (const float *)d_in[1];
    const int *I = (const int *)d_in[2];
    const float *W0 = (const float *)d_in[3];
    const float *b0 = (const float *)d_in[4];
    const float *g0 = (const float *)d_in[5];
    const float *be0 = (const float *)d_in[6];
    const float *W1 = (const float *)d_in[7];
    const float *b1 = (const float *)d_in[8];
    const float *g1 = (const float *)d_in[9];
    const float *be1 = (const float *)d_in[10];
    const float *Wf = (const float *)d_in[11];
    const float *bf = (const float *)d_in[12];
    const float *Wa = (const float *)d_in[13];
    const float *ba = (const float *)d_in[14];
    const float *Wout = (const float *)d_in[15];
    const float *bout = (const float *)d_in[16];
    float *out = (float *)d_out;

    float *y0t, *zp, *y1t;
    cudaGetSymbolAddress((void **)&y0t, dY0T);
    cudaGetSymbolAddress((void **)&zp, dZP);
    cudaGetSymbolAddress((void **)&y1t, dY1T);

    const int smem_bytes = NSTAGE * (BM * LDA + 64 * LDB) * 4;  // 110592
    cudaFuncSetAttribute(gemm_tf32, cudaFuncAttributeMaxDynamicSharedMemorySize,
                         smem_bytes);

    init_kernel<<<64, 256>>>();
    zmax_kernel<<<NNODES / 256, 256>>>(X, I);
    zexp_kernel<<<NNODES / 256, 256>>>(X, I);
    y0t_kernel<<<NNODES / 8, dim3(32, 8)>>>(X, W0);
    gemm_tf32<<<dim3(NNODES / BM, NSPLIT), 256, smem_bytes>>>(A, y0t, zp);
    mid_kernel<<<NNODES / 8, dim3(32, 8)>>>(b0, g0, be0, W1);
    gemm_tf32<<<dim3(NNODES / BM, NSPLIT), 256, smem_bytes>>>(A, y1t, zp);
    epi2_kernel<<<NNODES / 8, dim3(32, 8)>>>(I, b1, g1, be1, Wf, bf, Wa, ba);
    final_kernel<<<(GSEG + 63) / 64, 64>>>(Wout, bout, out);
}